// round 11
// baseline (speedup 1.0000x reference)
#include <cuda_runtime.h>
#include <cuda_fp16.h>
#include <mma.h>
#include <math.h>

using namespace nvcuda;

#define TT     2048
#define INDIM  1024
#define HH     2048
#define G4     8192

#define NCTA   148
#define UPC    14              // hidden units per CTA (148*14 = 2072 >= 2048)
#define NTHR   1024

// ---- scan smem layout (bytes) ----
#define SMEM_W_BYTES (6 * HH * 8 * 2)            // 48 rows fp16, 6 groups of 8: 196608
#define OFF_HX    (SMEM_W_BYTES)                 // 2048 half2 = 8192
#define OFF_DTP   (OFF_HX + HH * 4)              // 2048 float = 8192
#define OFF_XGP   (OFF_DTP + HH * 4)             // 2*64 float = 512
#define OFF_PART  (OFF_XGP + 128 * 4)            // 2*32*8 float = 2048
#define OFF_BIAS  (OFF_PART + 512 * 4)           // 64 float   = 256
#define SMEM_BYTES (OFF_BIAS + 64 * 4)

// ---------------- device scratch (static, allocation-free) ----------------
__device__ float  g_xg[(size_t)TT * G4];             // 64MB (pure x@Wih^T, no bias)
__device__ float  g_hs[(size_t)TT * HH];             // 16MB (raw h for attention)
__device__ __align__(16) __half g_Wspill[(size_t)NCTA * HH * 8];  // rows 48..55 per CTA
__device__ unsigned g_hxw[2][HH];                    // tagged h*gamma words, parity buffered
__device__ __align__(16) __half g_xh[(size_t)TT * INDIM];    // 4MB  x fp16
__device__ __align__(16) __half g_wh[(size_t)G4 * INDIM];    // 16MB Wih fp16
__device__ float  g_attn[TT];
__device__ float  g_w[TT];

__device__ __forceinline__ unsigned ld_relaxed_u32(const unsigned* p) {
    unsigned v;
    asm volatile("ld.relaxed.gpu.u32 %0, [%1];" : "=r"(v) : "l"(p) : "memory");
    return v;
}
__device__ __forceinline__ void st_relaxed_u32(unsigned* p, unsigned v) {
    asm volatile("st.relaxed.gpu.u32 [%0], %1;" :: "l"(p), "r"(v) : "memory");
}
__device__ __forceinline__ float sigmoid_f(float x) {
    return __fdividef(1.f, 1.f + __expf(-x));
}
__device__ __forceinline__ float tanh_f(float x) {
    return __fdividef(2.f, 1.f + __expf(-2.f * x)) - 1.f;
}

// Reduce 8 fp32 values across a warp with 9 shfls (split-butterfly).
__device__ __forceinline__ void warp_reduce8(float v[8], int lane, float* out) {
    const unsigned FULL = 0xffffffffu;
    bool b4 = (lane & 16) != 0;
    float k0 = b4 ? v[4] : v[0], g0 = b4 ? v[0] : v[4];
    float k1 = b4 ? v[5] : v[1], g1 = b4 ? v[1] : v[5];
    float k2 = b4 ? v[6] : v[2], g2 = b4 ? v[2] : v[6];
    float k3 = b4 ? v[7] : v[3], g3 = b4 ? v[3] : v[7];
    k0 += __shfl_xor_sync(FULL, g0, 16);
    k1 += __shfl_xor_sync(FULL, g1, 16);
    k2 += __shfl_xor_sync(FULL, g2, 16);
    k3 += __shfl_xor_sync(FULL, g3, 16);
    bool b3 = (lane & 8) != 0;
    float m0 = b3 ? k2 : k0, n0 = b3 ? k0 : k2;
    float m1 = b3 ? k3 : k1, n1 = b3 ? k1 : k3;
    m0 += __shfl_xor_sync(FULL, n0, 8);
    m1 += __shfl_xor_sync(FULL, n1, 8);
    bool b2 = (lane & 4) != 0;
    float p = b2 ? m1 : m0;
    float q = b2 ? m0 : m1;
    p += __shfl_xor_sync(FULL, q, 4);
    p += __shfl_xor_sync(FULL, p, 2);
    p += __shfl_xor_sync(FULL, p, 1);
    if ((lane & 3) == 0) {
        int j = ((lane >> 4) & 1) * 4 + ((lane >> 3) & 1) * 2 + ((lane >> 2) & 1);
        out[j] = p;
    }
}

// ======================= fp32 -> fp16 conversion =======================
__global__ __launch_bounds__(256) void conv_half(const float* __restrict__ src,
                                                 __half* __restrict__ dst, int n) {
    int i = (blockIdx.x * 256 + threadIdx.x) * 4;
    if (i < n) {
        float4 v = *(const float4*)(src + i);
        *(__half2*)(dst + i)     = __floats2half2_rn(v.x, v.y);
        *(__half2*)(dst + i + 2) = __floats2half2_rn(v.z, v.w);
    }
}

// ======== prep: spill pack + h0 tagged publish into g_hxw[0] ========
__global__ __launch_bounds__(256) void prep_spill(const float* __restrict__ Whh,
                                                  const float* __restrict__ h0) {
    int b = blockIdx.x;
    int u0 = b * UPC;
    for (int idx = threadIdx.x; idx < HH * 8; idx += 256) {
        int rg  = idx & 7;
        int col = idx >> 3;
        int r   = 48 + rg;
        int k    = r >> 2;
        int gate = r & 3;
        int u = u0 + k;
        float w = 0.f;
        if (u < HH) w = Whh[((size_t)gate * HH + u) * HH + col];
        g_Wspill[((size_t)b * HH + col) * 8 + rg] = __float2half(w);
    }
    if (b == 0) {
        for (int j = threadIdx.x; j < HH; j += 256) {
            // step 0 consumes tag 0; gamma = 1
            unsigned w = (unsigned)__half_as_ushort(__float2half(h0[j]));
            g_hxw[0][j] = w;   // tag 0 in high bits
        }
    }
}

// ======================= xg GEMM: wmma fp16, 128x128x32 tiles =======================
#define GBM 128
#define GBN 128
#define GBK 32
#define GPAD 8

__global__ __launch_bounds__(256) void gemm_xg_wmma() {
    __shared__ __half As[GBM][GBK + GPAD];
    __shared__ __half Bs[GBN][GBK + GPAD];
    const int tid = threadIdx.x;
    const int warp = tid >> 5;
    const int wm = warp & 1;      // 0..1 (m)
    const int wn = warp >> 1;     // 0..3 (n)
    const int m0 = blockIdx.y * GBM;
    const int n0 = blockIdx.x * GBN;

    wmma::fragment<wmma::accumulator, 16, 16, 16, float> acc[4][2];
#pragma unroll
    for (int i = 0; i < 4; i++)
#pragma unroll
        for (int j = 0; j < 2; j++) wmma::fill_fragment(acc[i][j], 0.f);

    const int lr = tid >> 1;             // 0..127
    const int lc = (tid & 1) * 16;       // 0 or 16

    for (int k0 = 0; k0 < INDIM; k0 += GBK) {
        *(uint4*)&As[lr][lc]     = *(const uint4*)&g_xh[(size_t)(m0 + lr) * INDIM + k0 + lc];
        *(uint4*)&As[lr][lc + 8] = *(const uint4*)&g_xh[(size_t)(m0 + lr) * INDIM + k0 + lc + 8];
        *(uint4*)&Bs[lr][lc]     = *(const uint4*)&g_wh[(size_t)(n0 + lr) * INDIM + k0 + lc];
        *(uint4*)&Bs[lr][lc + 8] = *(const uint4*)&g_wh[(size_t)(n0 + lr) * INDIM + k0 + lc + 8];
        __syncthreads();
#pragma unroll
        for (int kk = 0; kk < GBK; kk += 16) {
            wmma::fragment<wmma::matrix_a, 16, 16, 16, __half, wmma::row_major> af[4];
            wmma::fragment<wmma::matrix_b, 16, 16, 16, __half, wmma::col_major> bf[2];
#pragma unroll
            for (int i = 0; i < 4; i++)
                wmma::load_matrix_sync(af[i], &As[wm * 64 + i * 16][kk], GBK + GPAD);
#pragma unroll
            for (int j = 0; j < 2; j++)
                wmma::load_matrix_sync(bf[j], &Bs[wn * 32 + j * 16][kk], GBK + GPAD);
#pragma unroll
            for (int i = 0; i < 4; i++)
#pragma unroll
                for (int j = 0; j < 2; j++)
                    wmma::mma_sync(acc[i][j], af[i], bf[j], acc[i][j]);
        }
        __syncthreads();
    }
#pragma unroll
    for (int i = 0; i < 4; i++)
#pragma unroll
        for (int j = 0; j < 2; j++)
            wmma::store_matrix_sync(
                &g_xg[(size_t)(m0 + wm * 64 + i * 16) * G4 + n0 + wn * 32 + j * 16],
                acc[i][j], G4, wmma::mem_row_major);
}

// ======================= persistent LSTM scan =======================
__global__ void __launch_bounds__(NTHR, 1) lstm_scan(const float* __restrict__ Whh,
                                                     const float* __restrict__ time_,
                                                     const float* __restrict__ dwp,
                                                     const float* __restrict__ dbp,
                                                     const float* __restrict__ c0in,
                                                     const float* __restrict__ bih,
                                                     const float* __restrict__ bhh) {
    extern __shared__ __align__(16) char smem_raw[];
    __half*  W_s    = (__half*)smem_raw;
    __half2* hx_s   = (__half2*)(smem_raw + OFF_HX);
    float*   dtp_s  = (float*)(smem_raw + OFF_DTP);
    float*   xgp_s  = (float*)(smem_raw + OFF_XGP);    // [2][64]
    float*   part_s = (float*)(smem_raw + OFF_PART);   // [2][32][8]
    float*   bias_s = (float*)(smem_raw + OFF_BIAS);   // [64]

    const int tid = threadIdx.x;
    const int b   = blockIdx.x;
    const int u0  = b * UPC;
    const int warp = tid >> 5, lane = tid & 31;

    // ---- prologue: stage 48 rows into smem fp16, packed [grp][col][8] ----
    for (int r = 0; r < 48; r++) {
        int k = r >> 2, gate = r & 3;
        int u = u0 + k;
        int grp = r >> 3, rg = r & 7;
        __half* dst = W_s + (size_t)grp * (HH * 8) + rg;
        if (u < HH) {
            const float* src = Whh + ((size_t)gate * HH + u) * HH;
            for (int c = tid; c < HH; c += NTHR) dst[(size_t)c * 8] = __float2half(src[c]);
        } else {
            for (int c = tid; c < HH; c += NTHR) dst[(size_t)c * 8] = __float2half(0.f);
        }
    }
    // dtp_s[t] = time[t-1] - time[t-2] for t>=2, else 0
    {
        int t0 = tid;
        dtp_s[t0] = (t0 >= 2) ? (time_[t0 - 1] - time_[t0 - 2]) : 0.f;
        int t1 = tid + 1024;
        dtp_s[t1] = time_[t1 - 1] - time_[t1 - 2];
    }
    // bias + xg(0) into buffer 0
    if (tid < 64) {
        float bias = 0.f, xv = 0.f;
        if (tid < 56) {
            int k = tid >> 2, gate = tid & 3;
            int u = u0 + k;
            if (u < HH) {
                bias = bih[(size_t)gate * HH + u] + bhh[(size_t)gate * HH + u];
                xv = g_xg[(size_t)gate * HH + u] + bias;
            }
        }
        bias_s[tid] = bias;
        xgp_s[tid] = xv;
    }

    // gate-lane registers: c, dw, db for owned unit
    float c_reg = 0.f, dw_reg = 0.f, db_reg = 0.f;
    int   my_u = HH;
    if (warp < 2 && (lane & 3) == 0) {
        int r = warp * 32 + lane;
        if (r < 56) {
            int unit = r >> 2;
            int u = u0 + unit;
            if (u < HH) {
                my_u  = u;
                c_reg = c0in[u];
                dw_reg = dwp[u];
                db_reg = dbp[u];
            }
        }
    }
    __syncthreads();

    int grp, cbase;
    if (warp < 24) { grp = warp >> 2; cbase = (warp & 3) * 512; }
    else           { grp = 6;         cbase = (warp - 24) * 256; }

    for (int t = 0; t < TT; t++) {
        const int parity = t & 1;
        // ---- A: poll-stage h*gamma (tag == t means ready) ----
        {
            const unsigned* src = g_hxw[parity];
            unsigned want = (unsigned)t;
            unsigned v0 = ld_relaxed_u32(&src[tid]);
            unsigned spins = 0u;
            while ((v0 >> 16) != want) {
                v0 = ld_relaxed_u32(&src[tid]);
                if (++spins > (1u << 24)) break;
            }
            unsigned v1 = ld_relaxed_u32(&src[tid + 1024]);
            spins = 0u;
            while ((v1 >> 16) != want) {
                v1 = ld_relaxed_u32(&src[tid + 1024]);
                if (++spins > (1u << 24)) break;
            }
            ((unsigned*)hx_s)[tid]        = __byte_perm(v0, v0, 0x1010);
            ((unsigned*)hx_s)[tid + 1024] = __byte_perm(v1, v1, 0x1010);
        }
        __syncthreads();

        // ---- B: HFMA2 accumulate, dual banks ----
        float s[8];
        {
            __half2 a0[4], a1[4];
            const __half2 z = __float2half2_rn(0.f);
#pragma unroll
            for (int p = 0; p < 4; p++) { a0[p] = z; a1[p] = z; }

            if (grp < 6) {
                const __half* wb = W_s + (size_t)grp * (HH * 8);
#pragma unroll
                for (int it = 0; it < 16; it++) {
                    int col = cbase + it * 32 + lane;
                    uint4 w = *(const uint4*)(wb + (size_t)col * 8);
                    __half2 h2 = hx_s[col];
                    __half2* wp = (__half2*)&w;
                    if (it & 1) {
                        a1[0] = __hfma2(wp[0], h2, a1[0]);
                        a1[1] = __hfma2(wp[1], h2, a1[1]);
                        a1[2] = __hfma2(wp[2], h2, a1[2]);
                        a1[3] = __hfma2(wp[3], h2, a1[3]);
                    } else {
                        a0[0] = __hfma2(wp[0], h2, a0[0]);
                        a0[1] = __hfma2(wp[1], h2, a0[1]);
                        a0[2] = __hfma2(wp[2], h2, a0[2]);
                        a0[3] = __hfma2(wp[3], h2, a0[3]);
                    }
                }
            } else {
                const __half* wb = g_Wspill + (size_t)b * (HH * 8);
#pragma unroll
                for (int it = 0; it < 8; it++) {
                    int col = cbase + it * 32 + lane;
                    uint4 w = __ldg((const uint4*)(wb + (size_t)col * 8));
                    __half2 h2 = hx_s[col];
                    __half2* wp = (__half2*)&w;
                    if (it & 1) {
                        a1[0] = __hfma2(wp[0], h2, a1[0]);
                        a1[1] = __hfma2(wp[1], h2, a1[1]);
                        a1[2] = __hfma2(wp[2], h2, a1[2]);
                        a1[3] = __hfma2(wp[3], h2, a1[3]);
                    } else {
                        a0[0] = __hfma2(wp[0], h2, a0[0]);
                        a0[1] = __hfma2(wp[1], h2, a0[1]);
                        a0[2] = __hfma2(wp[2], h2, a0[2]);
                        a0[3] = __hfma2(wp[3], h2, a0[3]);
                    }
                }
            }
#pragma unroll
            for (int p = 0; p < 4; p++) {
                float2 fa = __half22float2(a0[p]);
                float2 fb = __half22float2(a1[p]);
                s[2 * p]     = fa.x + fb.x;
                s[2 * p + 1] = fa.y + fb.y;
            }
        }
        warp_reduce8(s, lane, part_s + parity * 256 + warp * 8);
        __syncthreads();

        // ---- C: gate phase (warps 0-1), xg prefetch (warp 2) ----
        if (warp < 2) {
            const float* pp = part_s + parity * 256;
            int r  = warp * 32 + lane;
            int rr = (r < 56) ? r : 55;
            float tot = xgp_s[parity * 64 + rr];
            if (rr < 48) {
                int g = rr >> 3, slot = rr & 7;
                tot += pp[(4 * g + 0) * 8 + slot] + pp[(4 * g + 1) * 8 + slot]
                     + pp[(4 * g + 2) * 8 + slot] + pp[(4 * g + 3) * 8 + slot];
            } else {
                int slot = rr - 48;
#pragma unroll
                for (int i = 0; i < 8; i++) tot += pp[(24 + i) * 8 + slot];
            }
            int role = rr & 3;
            float act = (role == 2) ? tanh_f(tot) : sigmoid_f(tot);
            int base = lane & ~3;
            float f_ = __shfl_sync(0xffffffffu, act, base + 1, 32);
            float gg = __shfl_sync(0xffffffffu, act, base + 2, 32);
            float o_ = __shfl_sync(0xffffffffu, act, base + 3, 32);
            if (my_u < HH) {
                c_reg = f_ * c_reg + act * gg;     // act = i gate on these lanes
                float th = tanh_f(c_reg);
                float h = o_ * th;
                g_hs[(size_t)t * HH + my_u] = h;
                if (t + 1 < TT) {
                    float z = fmaxf(dtp_s[t + 1] * dw_reg + db_reg, 0.f);
                    float gam = __expf(-z);
                    __half hb = __float2half(h * gam);
                    unsigned w = ((unsigned)(t + 1) << 16) |
                                 (unsigned)__half_as_ushort(hb);
                    st_relaxed_u32(&g_hxw[(t + 1) & 1][my_u], w);
                }
            }
        } else if (warp == 2 && t + 1 < TT) {
            for (int q = lane; q < 56; q += 32) {
                int k = q >> 2, gate = q & 3;
                int u = u0 + k;
                xgp_s[((t + 1) & 1) * 64 + q] =
                    (u < HH) ? g_xg[(size_t)(t + 1) * G4 + (size_t)gate * HH + u] + bias_s[q] : 0.f;
            }
        }
        // no grid barrier: next step's tag-poll self-throttles
    }
}

// ======================= attention pooling =======================
__global__ __launch_bounds__(256) void attn_scores() {
    __shared__ float red[8];
    const float* a = g_hs + (size_t)blockIdx.x * HH;
    const float* bf = g_hs + (size_t)(TT - 1) * HH;
    float s = 0.f;
    for (int j = threadIdx.x; j < HH; j += 256) s += a[j] * bf[j];
    for (int o = 16; o; o >>= 1) s += __shfl_xor_sync(0xffffffffu, s, o);
    if ((threadIdx.x & 31) == 0) red[threadIdx.x >> 5] = s;
    __syncthreads();
    if (threadIdx.x == 0) {
        float t = 0.f;
        for (int w = 0; w < 8; w++) t += red[w];
        g_attn[blockIdx.x] = t;
    }
}

__global__ __launch_bounds__(1024) void attn_softmax() {
    __shared__ float rmax[32], rsum[32];
    int tid = threadIdx.x;
    float v0 = g_attn[tid], v1 = g_attn[tid + 1024];
    float m = fmaxf(v0, v1);
    for (int o = 16; o; o >>= 1) m = fmaxf(m, __shfl_xor_sync(0xffffffffu, m, o));
    if ((tid & 31) == 0) rmax[tid >> 5] = m;
    __syncthreads();
    if (tid < 32) {
        float x = rmax[tid];
        for (int o = 16; o; o >>= 1) x = fmaxf(x, __shfl_xor_sync(0xffffffffu, x, o));
        rmax[tid] = x;
    }
    __syncthreads();
    float M = rmax[0];
    float e0 = expf(v0 - M), e1 = expf(v1 - M);
    float s = e0 + e1;
    for (int o = 16; o; o >>= 1) s += __shfl_xor_sync(0xffffffffu, s, o);
    if ((tid & 31) == 0) rsum[tid >> 5] = s;
    __syncthreads();
    if (tid < 32) {
        float x = rsum[tid];
        for (int o = 16; o; o >>= 1) x += __shfl_xor_sync(0xffffffffu, x, o);
        rsum[tid] = x;
    }
    __syncthreads();
    float inv = 1.f / rsum[0];
    g_w[tid] = e0 * inv;
    g_w[tid + 1024] = e1 * inv;
}

__global__ __launch_bounds__(256) void attn_context(float* __restrict__ out) {
    __shared__ float ws[TT];
    for (int i = threadIdx.x; i < TT; i += 256) ws[i] = g_w[i];
    __syncthreads();
    int j = blockIdx.x * 256 + threadIdx.x;
    float acc = 0.f;
#pragma unroll 8
    for (int t = 0; t < TT; t++) acc += ws[t] * g_hs[(size_t)t * HH + j];
    out[j] = acc;
}

// ======================= launch =======================
extern "C" void kernel_launch(void* const* d_in, const int* in_sizes, int n_in,
                              void* d_out, int out_size) {
    const float* x     = (const float*)d_in[0];
    const float* time_ = (const float*)d_in[1];
    const float* Wih   = (const float*)d_in[2];
    const float* Whh   = (const float*)d_in[3];
    const float* bih   = (const float*)d_in[4];
    const float* bhh   = (const float*)d_in[5];
    const float* dw    = (const float*)d_in[6];
    const float* db    = (const float*)d_in[7];
    const float* h0    = (const float*)d_in[8];
    const float* c0    = (const float*)d_in[9];
    float* out = (float*)d_out;

    cudaFuncSetAttribute(lstm_scan, cudaFuncAttributeMaxDynamicSharedMemorySize, SMEM_BYTES);

    __half* d_xh;  cudaGetSymbolAddress((void**)&d_xh, g_xh);
    __half* d_wh;  cudaGetSymbolAddress((void**)&d_wh, g_wh);

    conv_half<<<(TT * INDIM / 4 + 255) / 256, 256>>>(x, d_xh, TT * INDIM);
    conv_half<<<(G4 * INDIM / 4 + 255) / 256, 256>>>(Wih, d_wh, G4 * INDIM);
    prep_spill<<<NCTA, 256>>>(Whh, h0);
    gemm_xg_wmma<<<dim3(G4 / GBN, TT / GBM), 256>>>();
    lstm_scan<<<NCTA, NTHR, SMEM_BYTES>>>(Whh, time_, dw, db, c0, bih, bhh);
    attn_scores<<<TT, 256>>>();
    attn_softmax<<<1, 1024>>>();
    attn_context<<<HH / 256, 256>>>(out);
}

// round 12
// speedup vs baseline: 1.3806x; 1.3806x over previous
#include <cuda_runtime.h>
#include <cuda_fp16.h>
#include <mma.h>
#include <math.h>

using namespace nvcuda;

#define TT     2048
#define INDIM  1024
#define HH     2048
#define G4     8192

#define NCTA   148
#define UPC    14              // hidden units per CTA (148*14 = 2072 >= 2048)
#define NTHR   1024

// ---- scan smem layout (bytes) ----
#define SMEM_W_BYTES (6 * HH * 8 * 2)            // 48 rows fp16, 6 groups of 8: 196608
#define OFF_HX    (SMEM_W_BYTES)                 // 2048 half2 = 8192
#define OFF_DTP   (OFF_HX + HH * 4)              // 2048 float = 8192
#define OFF_XGP   (OFF_DTP + HH * 4)             // 2*64 float = 512
#define OFF_PART  (OFF_XGP + 128 * 4)            // 32*8 float = 1024
#define OFF_BIAS  (OFF_PART + 256 * 4)           // 64 float   = 256
#define SMEM_BYTES (OFF_BIAS + 64 * 4)

// ---------------- device scratch (static, allocation-free) ----------------
__device__ float  g_xg[(size_t)TT * G4];             // 64MB (pure x@Wih^T, no bias)
__device__ float  g_hs[(size_t)TT * HH];             // 16MB (raw h for attention)
__device__ __align__(16) __half g_Wspill[(size_t)NCTA * HH * 8];  // rows 48..55 per CTA
__device__ __align__(8) __half2 g_hx[2][HH];         // h*gamma exchange, parity buffered
__device__ __align__(16) __half g_xh[(size_t)TT * INDIM];    // 4MB  x fp16
__device__ __align__(16) __half g_wh[(size_t)G4 * INDIM];    // 16MB Wih fp16
__device__ float  g_attn[TT];
__device__ float  g_w[TT];
__device__ unsigned g_arrive;

__device__ __forceinline__ unsigned ld_relaxed_u32(const unsigned* p) {
    unsigned v;
    asm volatile("ld.relaxed.gpu.u32 %0, [%1];" : "=r"(v) : "l"(p) : "memory");
    return v;
}
__device__ __forceinline__ unsigned ld_acquire_u32(const unsigned* p) {
    unsigned v;
    asm volatile("ld.acquire.gpu.u32 %0, [%1];" : "=r"(v) : "l"(p) : "memory");
    return v;
}
__device__ __forceinline__ void red_release_add_u32(unsigned* p, unsigned v) {
    asm volatile("red.release.gpu.add.u32 [%0], %1;" :: "l"(p), "r"(v) : "memory");
}
__device__ __forceinline__ float sigmoid_f(float x) {
    return __fdividef(1.f, 1.f + __expf(-x));
}
__device__ __forceinline__ float tanh_f(float x) {
    return __fdividef(2.f, 1.f + __expf(-2.f * x)) - 1.f;
}

// Reduce 8 fp32 values across a warp with 9 shfls (split-butterfly).
__device__ __forceinline__ void warp_reduce8(float v[8], int lane, float* out) {
    const unsigned FULL = 0xffffffffu;
    bool b4 = (lane & 16) != 0;
    float k0 = b4 ? v[4] : v[0], g0 = b4 ? v[0] : v[4];
    float k1 = b4 ? v[5] : v[1], g1 = b4 ? v[1] : v[5];
    float k2 = b4 ? v[6] : v[2], g2 = b4 ? v[2] : v[6];
    float k3 = b4 ? v[7] : v[3], g3 = b4 ? v[3] : v[7];
    k0 += __shfl_xor_sync(FULL, g0, 16);
    k1 += __shfl_xor_sync(FULL, g1, 16);
    k2 += __shfl_xor_sync(FULL, g2, 16);
    k3 += __shfl_xor_sync(FULL, g3, 16);
    bool b3 = (lane & 8) != 0;
    float m0 = b3 ? k2 : k0, n0 = b3 ? k0 : k2;
    float m1 = b3 ? k3 : k1, n1 = b3 ? k1 : k3;
    m0 += __shfl_xor_sync(FULL, n0, 8);
    m1 += __shfl_xor_sync(FULL, n1, 8);
    bool b2 = (lane & 4) != 0;
    float p = b2 ? m1 : m0;
    float q = b2 ? m0 : m1;
    p += __shfl_xor_sync(FULL, q, 4);
    p += __shfl_xor_sync(FULL, p, 2);
    p += __shfl_xor_sync(FULL, p, 1);
    if ((lane & 3) == 0) {
        int j = ((lane >> 4) & 1) * 4 + ((lane >> 3) & 1) * 2 + ((lane >> 2) & 1);
        out[j] = p;
    }
}

// ======================= fp32 -> fp16 conversion =======================
__global__ __launch_bounds__(256) void conv_half(const float* __restrict__ src,
                                                 __half* __restrict__ dst, int n) {
    int i = (blockIdx.x * 256 + threadIdx.x) * 4;
    if (i < n) {
        float4 v = *(const float4*)(src + i);
        *(__half2*)(dst + i)     = __floats2half2_rn(v.x, v.y);
        *(__half2*)(dst + i + 2) = __floats2half2_rn(v.z, v.w);
    }
}

// ======== prep: spill pack + barrier reset + h0 broadcast into g_hx[0] ========
__global__ __launch_bounds__(256) void prep_spill(const float* __restrict__ Whh,
                                                  const float* __restrict__ h0) {
    int b = blockIdx.x;
    int u0 = b * UPC;
    for (int idx = threadIdx.x; idx < HH * 8; idx += 256) {
        int rg  = idx & 7;
        int col = idx >> 3;
        int r   = 48 + rg;
        int k    = r >> 2;
        int gate = r & 3;
        int u = u0 + k;
        float w = 0.f;
        if (u < HH) w = Whh[((size_t)gate * HH + u) * HH + col];
        g_Wspill[((size_t)b * HH + col) * 8 + rg] = __float2half(w);
    }
    if (b == 0) {
        if (threadIdx.x == 0) g_arrive = 0u;
        for (int j = threadIdx.x; j < HH; j += 256)
            g_hx[0][j] = __float2half2_rn(h0[j]);   // step 0: gamma = 1
    }
}

// ======================= xg GEMM: wmma fp16, 128x128x32 tiles =======================
#define GBM 128
#define GBN 128
#define GBK 32
#define GPAD 8

__global__ __launch_bounds__(256) void gemm_xg_wmma() {
    __shared__ __half As[GBM][GBK + GPAD];
    __shared__ __half Bs[GBN][GBK + GPAD];
    const int tid = threadIdx.x;
    const int warp = tid >> 5;
    const int wm = warp & 1;      // 0..1 (m)
    const int wn = warp >> 1;     // 0..3 (n)
    const int m0 = blockIdx.y * GBM;
    const int n0 = blockIdx.x * GBN;

    wmma::fragment<wmma::accumulator, 16, 16, 16, float> acc[4][2];
#pragma unroll
    for (int i = 0; i < 4; i++)
#pragma unroll
        for (int j = 0; j < 2; j++) wmma::fill_fragment(acc[i][j], 0.f);

    const int lr = tid >> 1;             // 0..127
    const int lc = (tid & 1) * 16;       // 0 or 16

    for (int k0 = 0; k0 < INDIM; k0 += GBK) {
        *(uint4*)&As[lr][lc]     = *(const uint4*)&g_xh[(size_t)(m0 + lr) * INDIM + k0 + lc];
        *(uint4*)&As[lr][lc + 8] = *(const uint4*)&g_xh[(size_t)(m0 + lr) * INDIM + k0 + lc + 8];
        *(uint4*)&Bs[lr][lc]     = *(const uint4*)&g_wh[(size_t)(n0 + lr) * INDIM + k0 + lc];
        *(uint4*)&Bs[lr][lc + 8] = *(const uint4*)&g_wh[(size_t)(n0 + lr) * INDIM + k0 + lc + 8];
        __syncthreads();
#pragma unroll
        for (int kk = 0; kk < GBK; kk += 16) {
            wmma::fragment<wmma::matrix_a, 16, 16, 16, __half, wmma::row_major> af[4];
            wmma::fragment<wmma::matrix_b, 16, 16, 16, __half, wmma::col_major> bf[2];
#pragma unroll
            for (int i = 0; i < 4; i++)
                wmma::load_matrix_sync(af[i], &As[wm * 64 + i * 16][kk], GBK + GPAD);
#pragma unroll
            for (int j = 0; j < 2; j++)
                wmma::load_matrix_sync(bf[j], &Bs[wn * 32 + j * 16][kk], GBK + GPAD);
#pragma unroll
            for (int i = 0; i < 4; i++)
#pragma unroll
                for (int j = 0; j < 2; j++)
                    wmma::mma_sync(acc[i][j], af[i], bf[j], acc[i][j]);
        }
        __syncthreads();
    }
#pragma unroll
    for (int i = 0; i < 4; i++)
#pragma unroll
        for (int j = 0; j < 2; j++)
            wmma::store_matrix_sync(
                &g_xg[(size_t)(m0 + wm * 64 + i * 16) * G4 + n0 + wn * 32 + j * 16],
                acc[i][j], G4, wmma::mem_row_major);
}

// ======================= persistent LSTM scan =======================
__global__ void __launch_bounds__(NTHR, 1) lstm_scan(const float* __restrict__ Whh,
                                                     const float* __restrict__ time_,
                                                     const float* __restrict__ dwp,
                                                     const float* __restrict__ dbp,
                                                     const float* __restrict__ c0in,
                                                     const float* __restrict__ bih,
                                                     const float* __restrict__ bhh) {
    extern __shared__ __align__(16) char smem_raw[];
    __half*  W_s    = (__half*)smem_raw;
    __half2* hx_s   = (__half2*)(smem_raw + OFF_HX);
    float*   dtp_s  = (float*)(smem_raw + OFF_DTP);
    float*   xgp_s  = (float*)(smem_raw + OFF_XGP);    // [2][64]
    float*   part_s = (float*)(smem_raw + OFF_PART);   // [32][8]
    float*   bias_s = (float*)(smem_raw + OFF_BIAS);   // [64]

    const int tid = threadIdx.x;
    const int b   = blockIdx.x;
    const int u0  = b * UPC;
    const int warp = tid >> 5, lane = tid & 31;

    // ---- prologue: stage 48 rows into smem fp16, packed [grp][col][8] ----
    for (int r = 0; r < 48; r++) {
        int k = r >> 2, gate = r & 3;
        int u = u0 + k;
        int grp = r >> 3, rg = r & 7;
        __half* dst = W_s + (size_t)grp * (HH * 8) + rg;
        if (u < HH) {
            const float* src = Whh + ((size_t)gate * HH + u) * HH;
            for (int c = tid; c < HH; c += NTHR) dst[(size_t)c * 8] = __float2half(src[c]);
        } else {
            for (int c = tid; c < HH; c += NTHR) dst[(size_t)c * 8] = __float2half(0.f);
        }
    }
    // dtp_s[t] = time[t-1] - time[t-2] for t>=2, else 0
    {
        int t0 = tid;
        dtp_s[t0] = (t0 >= 2) ? (time_[t0 - 1] - time_[t0 - 2]) : 0.f;
        int t1 = tid + 1024;
        dtp_s[t1] = time_[t1 - 1] - time_[t1 - 2];
    }
    // bias + xg(0) into buffer 0
    if (tid < 64) {
        float bias = 0.f, xv = 0.f;
        if (tid < 56) {
            int k = tid >> 2, gate = tid & 3;
            int u = u0 + k;
            if (u < HH) {
                bias = bih[(size_t)gate * HH + u] + bhh[(size_t)gate * HH + u];
                xv = g_xg[(size_t)gate * HH + u] + bias;
            }
        }
        bias_s[tid] = bias;
        xgp_s[tid] = xv;
    }

    // gate-lane registers: c, dw, db for owned unit
    float c_reg = 0.f, dw_reg = 0.f, db_reg = 0.f;
    int   my_u = HH;
    if (warp < 2 && (lane & 3) == 0) {
        int r = warp * 32 + lane;
        if (r < 56) {
            int unit = r >> 2;
            int u = u0 + unit;
            if (u < HH) {
                my_u  = u;
                c_reg = c0in[u];
                dw_reg = dwp[u];
                db_reg = dbp[u];
            }
        }
    }
    __syncthreads();

    int grp, cbase;
    if (warp < 24) { grp = warp >> 2; cbase = (warp & 3) * 512; }
    else           { grp = 6;         cbase = (warp - 24) * 256; }

    for (int t = 0; t < TT; t++) {
        // ---- A: stage h*gamma (pre-multiplied by producer) ----
        {
            const unsigned* src = (const unsigned*)g_hx[t & 1];
            unsigned v0 = __ldcg(&src[tid]);
            unsigned v1 = __ldcg(&src[tid + 1024]);
            ((unsigned*)hx_s)[tid]        = v0;
            ((unsigned*)hx_s)[tid + 1024] = v1;
        }
        __syncthreads();

        // ---- B: HFMA2 accumulate, dual banks ----
        float s[8];
        {
            __half2 a0[4], a1[4];
            const __half2 z = __float2half2_rn(0.f);
#pragma unroll
            for (int p = 0; p < 4; p++) { a0[p] = z; a1[p] = z; }

            if (grp < 6) {
                const __half* wb = W_s + (size_t)grp * (HH * 8);
#pragma unroll
                for (int it = 0; it < 16; it++) {
                    int col = cbase + it * 32 + lane;
                    uint4 w = *(const uint4*)(wb + (size_t)col * 8);
                    __half2 h2 = hx_s[col];
                    __half2* wp = (__half2*)&w;
                    if (it & 1) {
                        a1[0] = __hfma2(wp[0], h2, a1[0]);
                        a1[1] = __hfma2(wp[1], h2, a1[1]);
                        a1[2] = __hfma2(wp[2], h2, a1[2]);
                        a1[3] = __hfma2(wp[3], h2, a1[3]);
                    } else {
                        a0[0] = __hfma2(wp[0], h2, a0[0]);
                        a0[1] = __hfma2(wp[1], h2, a0[1]);
                        a0[2] = __hfma2(wp[2], h2, a0[2]);
                        a0[3] = __hfma2(wp[3], h2, a0[3]);
                    }
                }
            } else {
                const __half* wb = g_Wspill + (size_t)b * (HH * 8);
#pragma unroll
                for (int it = 0; it < 8; it++) {
                    int col = cbase + it * 32 + lane;
                    uint4 w = __ldg((const uint4*)(wb + (size_t)col * 8));
                    __half2 h2 = hx_s[col];
                    __half2* wp = (__half2*)&w;
                    if (it & 1) {
                        a1[0] = __hfma2(wp[0], h2, a1[0]);
                        a1[1] = __hfma2(wp[1], h2, a1[1]);
                        a1[2] = __hfma2(wp[2], h2, a1[2]);
                        a1[3] = __hfma2(wp[3], h2, a1[3]);
                    } else {
                        a0[0] = __hfma2(wp[0], h2, a0[0]);
                        a0[1] = __hfma2(wp[1], h2, a0[1]);
                        a0[2] = __hfma2(wp[2], h2, a0[2]);
                        a0[3] = __hfma2(wp[3], h2, a0[3]);
                    }
                }
            }
#pragma unroll
            for (int p = 0; p < 4; p++) {
                float2 fa = __half22float2(a0[p]);
                float2 fb = __half22float2(a1[p]);
                s[2 * p]     = fa.x + fb.x;
                s[2 * p + 1] = fa.y + fb.y;
            }
        }
        warp_reduce8(s, lane, part_s + warp * 8);
        __syncthreads();

        // ---- C: gate phase (warps 0-1), xg prefetch (warps 2-3) ----
        if (warp < 2) {
            int r  = warp * 32 + lane;
            int rr = (r < 56) ? r : 55;
            float tot = xgp_s[(t & 1) * 64 + rr];
            if (rr < 48) {
                int g = rr >> 3, slot = rr & 7;
                tot += part_s[(4 * g + 0) * 8 + slot] + part_s[(4 * g + 1) * 8 + slot]
                     + part_s[(4 * g + 2) * 8 + slot] + part_s[(4 * g + 3) * 8 + slot];
            } else {
                int slot = rr - 48;
#pragma unroll
                for (int i = 0; i < 8; i++) tot += part_s[(24 + i) * 8 + slot];
            }
            int role = rr & 3;
            float act = (role == 2) ? tanh_f(tot) : sigmoid_f(tot);
            int base = lane & ~3;
            float f_ = __shfl_sync(0xffffffffu, act, base + 1, 32);
            float gg = __shfl_sync(0xffffffffu, act, base + 2, 32);
            float o_ = __shfl_sync(0xffffffffu, act, base + 3, 32);
            if (my_u < HH) {
                c_reg = f_ * c_reg + act * gg;     // act = i gate on these lanes
                float th = tanh_f(c_reg);
                float h = o_ * th;
                if (t + 1 < TT) {
                    // publish first: this is the inter-CTA critical path
                    float z = fmaxf(dtp_s[t + 1] * dw_reg + db_reg, 0.f);
                    float gam = __expf(-z);
                    g_hx[(t + 1) & 1][my_u] = __float2half2_rn(h * gam);
                }
                g_hs[(size_t)t * HH + my_u] = h;
            }
            if (t + 1 < TT) {
                // both gate warps' publishes done -> single release arrive
                asm volatile("bar.sync 3, 64;" ::: "memory");
                if (tid == 0) red_release_add_u32(&g_arrive, 1u);
            }
        } else if ((warp == 2 || warp == 3) && t + 1 < TT) {
            int q = (warp - 2) * 32 + lane;
            if (q < 56) {
                int k = q >> 2, gate = q & 3;
                int u = u0 + k;
                xgp_s[((t + 1) & 1) * 64 + q] =
                    (u < HH) ? g_xg[(size_t)(t + 1) * G4 + (size_t)gate * HH + u] + bias_s[q] : 0.f;
            }
        }

        // ---- D: grid barrier — single poller, relaxed spin + acquire once ----
        if (t + 1 < TT) {
            if (tid == 0) {
                unsigned target = (unsigned)NCTA * (unsigned)(t + 1);
                unsigned spins = 0u;
                while (ld_relaxed_u32(&g_arrive) < target) {
                    if (++spins > (1u << 22)) break;
                }
                (void)ld_acquire_u32(&g_arrive);   // establish ordering once
            }
            __syncthreads();
        }
    }
}

// ======================= attention pooling =======================
__global__ __launch_bounds__(256) void attn_scores() {
    __shared__ float red[8];
    const float* a = g_hs + (size_t)blockIdx.x * HH;
    const float* bf = g_hs + (size_t)(TT - 1) * HH;
    float s = 0.f;
    for (int j = threadIdx.x; j < HH; j += 256) s += a[j] * bf[j];
    for (int o = 16; o; o >>= 1) s += __shfl_xor_sync(0xffffffffu, s, o);
    if ((threadIdx.x & 31) == 0) red[threadIdx.x >> 5] = s;
    __syncthreads();
    if (threadIdx.x == 0) {
        float t = 0.f;
        for (int w = 0; w < 8; w++) t += red[w];
        g_attn[blockIdx.x] = t;
    }
}

__global__ __launch_bounds__(1024) void attn_softmax() {
    __shared__ float rmax[32], rsum[32];
    int tid = threadIdx.x;
    float v0 = g_attn[tid], v1 = g_attn[tid + 1024];
    float m = fmaxf(v0, v1);
    for (int o = 16; o; o >>= 1) m = fmaxf(m, __shfl_xor_sync(0xffffffffu, m, o));
    if ((tid & 31) == 0) rmax[tid >> 5] = m;
    __syncthreads();
    if (tid < 32) {
        float x = rmax[tid];
        for (int o = 16; o; o >>= 1) x = fmaxf(x, __shfl_xor_sync(0xffffffffu, x, o));
        rmax[tid] = x;
    }
    __syncthreads();
    float M = rmax[0];
    float e0 = expf(v0 - M), e1 = expf(v1 - M);
    float s = e0 + e1;
    for (int o = 16; o; o >>= 1) s += __shfl_xor_sync(0xffffffffu, s, o);
    if ((tid & 31) == 0) rsum[tid >> 5] = s;
    __syncthreads();
    if (tid < 32) {
        float x = rsum[tid];
        for (int o = 16; o; o >>= 1) x += __shfl_xor_sync(0xffffffffu, x, o);
        rsum[tid] = x;
    }
    __syncthreads();
    float inv = 1.f / rsum[0];
    g_w[tid] = e0 * inv;
    g_w[tid + 1024] = e1 * inv;
}

__global__ __launch_bounds__(256) void attn_context(float* __restrict__ out) {
    __shared__ float ws[TT];
    for (int i = threadIdx.x; i < TT; i += 256) ws[i] = g_w[i];
    __syncthreads();
    int j = blockIdx.x * 256 + threadIdx.x;
    float acc = 0.f;
#pragma unroll 8
    for (int t = 0; t < TT; t++) acc += ws[t] * g_hs[(size_t)t * HH + j];
    out[j] = acc;
}

// ======================= launch =======================
extern "C" void kernel_launch(void* const* d_in, const int* in_sizes, int n_in,
                              void* d_out, int out_size) {
    const float* x     = (const float*)d_in[0];
    const float* time_ = (const float*)d_in[1];
    const float* Wih   = (const float*)d_in[2];
    const float* Whh   = (const float*)d_in[3];
    const float* bih   = (const float*)d_in[4];
    const float* bhh   = (const float*)d_in[5];
    const float* dw    = (const float*)d_in[6];
    const float* db    = (const float*)d_in[7];
    const float* h0    = (const float*)d_in[8];
    const float* c0    = (const float*)d_in[9];
    float* out = (float*)d_out;

    cudaFuncSetAttribute(lstm_scan, cudaFuncAttributeMaxDynamicSharedMemorySize, SMEM_BYTES);

    __half* d_xh;  cudaGetSymbolAddress((void**)&d_xh, g_xh);
    __half* d_wh;  cudaGetSymbolAddress((void**)&d_wh, g_wh);

    conv_half<<<(TT * INDIM / 4 + 255) / 256, 256>>>(x, d_xh, TT * INDIM);
    conv_half<<<(G4 * INDIM / 4 + 255) / 256, 256>>>(Wih, d_wh, G4 * INDIM);
    prep_spill<<<NCTA, 256>>>(Whh, h0);
    gemm_xg_wmma<<<dim3(G4 / GBN, TT / GBM), 256>>>();
    lstm_scan<<<NCTA, NTHR, SMEM_BYTES>>>(Whh, time_, dw, db, c0, bih, bhh);
    attn_scores<<<TT, 256>>>();
    attn_softmax<<<1, 1024>>>();
    attn_context<<<HH / 256, 256>>>(out);
}